// round 4
// baseline (speedup 1.0000x reference)
#include <cuda_runtime.h>
#include <cuda_fp16.h>

// B=4, C=64, D=16, H=64, W=64, C8=8, k=38 -> thr = sorted_ascending[26]
#define EPSBN 1e-5f
typedef unsigned long long ull;

// ---------------- packed f32x2 helpers (FMA pipe only on this toolchain) ----
__device__ __forceinline__ ull pk(float lo, float hi) {
  ull r; asm("mov.b64 %0,{%1,%2};" : "=l"(r) : "f"(lo), "f"(hi)); return r;
}
__device__ __forceinline__ void upk(float& lo, float& hi, ull v) {
  asm("mov.b64 {%0,%1},%2;" : "=f"(lo), "=f"(hi) : "l"(v));
}
__device__ __forceinline__ ull fma2(ull a, ull b, ull c) {
  ull d; asm("fma.rn.f32x2 %0,%1,%2,%3;" : "=l"(d) : "l"(a), "l"(b), "l"(c)); return d;
}
__device__ __forceinline__ float silu_f(float v) {
  return v * (1.0f / (1.0f + __expf(-v)));
}

// ---------------- params ----------------
struct C2 {
  ull w1o[256];   // [c*4+j] = pk(w1t[c][2j], w1t[c][2j+1]), bn2 scale folded
  ull w2o[256];   // [c*4+j] = pk(w2[c][2j], w2[c][2j+1])
  ull b1o[4];     // pk(b1_eff[2j], b1_eff[2j+1])
  float b2[64];
  float alpha;
};
__device__   C2 g_c2;
__constant__ C2 c2;
__device__ __half g_y1[16777216];   // 32MB; same linear indexing as x

// ---------------- prep ----------------
__global__ void kprep(const float* __restrict__ wp1, const float* __restrict__ bp1,
                      const float* __restrict__ g2, const float* __restrict__ be2,
                      const float* __restrict__ m2, const float* __restrict__ v2,
                      const float* __restrict__ wp2, const float* __restrict__ bp2,
                      const float* __restrict__ alpha) {
  int tid = threadIdx.x;          // 256 threads
  int c = tid >> 2, j = tid & 3;
  int o0 = 2 * j, o1 = 2 * j + 1;
  float s2a = __ldg(g2 + o0) * rsqrtf(__ldg(v2 + o0) + EPSBN);
  float s2b = __ldg(g2 + o1) * rsqrtf(__ldg(v2 + o1) + EPSBN);
  g_c2.w1o[c * 4 + j] = pk(__ldg(wp1 + o0 * 64 + c) * s2a,
                           __ldg(wp1 + o1 * 64 + c) * s2b);
  g_c2.w2o[c * 4 + j] = pk(__ldg(wp2 + c * 8 + o0), __ldg(wp2 + c * 8 + o1));
  if (tid < 4) {
    int p0 = 2 * tid, p1 = 2 * tid + 1;
    float sa = __ldg(g2 + p0) * rsqrtf(__ldg(v2 + p0) + EPSBN);
    float sb = __ldg(g2 + p1) * rsqrtf(__ldg(v2 + p1) + EPSBN);
    g_c2.b1o[tid] = pk((__ldg(bp1 + p0) - __ldg(m2 + p0)) * sa + __ldg(be2 + p0),
                       (__ldg(bp1 + p1) - __ldg(m2 + p1)) * sb + __ldg(be2 + p1));
  }
  if (tid < 64) g_c2.b2[tid] = __ldg(bp2 + tid);
  if (tid == 0) g_c2.alpha = __ldg(alpha);
}

// ---------------- kernel 1: depthwise conv + BN + SiLU -> fp16 y1 ----------
#define PITCH 68
__global__ void __launch_bounds__(256)
k_dwconv(const float* __restrict__ x,
         const float* __restrict__ wdw,
         const float* __restrict__ g1, const float* __restrict__ be1,
         const float* __restrict__ m1, const float* __restrict__ v1) {
  __shared__ float tile[68 * PITCH];
  int p = blockIdx.x;               // ((b*64+c)*16+d)
  int c = (p >> 4) & 63;
  int tid = threadIdx.x;

  for (int i = tid; i < 68 * PITCH; i += 256) tile[i] = 0.f;
  __syncthreads();
  const float* xp = x + (size_t)p * 4096;
  #pragma unroll
  for (int it = 0; it < 4; it++) {
    int i = tid + it * 256;
    int h = i >> 4, q = i & 15;
    float4 v = *reinterpret_cast<const float4*>(xp + h * 64 + q * 4);
    float* dst = &tile[(h + 2) * PITCH + q * 4 + 2];
    dst[0] = v.x; dst[1] = v.y; dst[2] = v.z; dst[3] = v.w;
  }
  __syncthreads();

  float s1 = __ldg(g1 + c) * rsqrtf(__ldg(v1 + c) + EPSBN);
  float t1 = __ldg(be1 + c) - __ldg(m1 + c) * s1;
  ull W[25];
  #pragma unroll
  for (int j = 0; j < 25; j++) {
    float w = __ldg(wdw + c * 25 + j) * s1;
    W[j] = pk(w, w);
  }

  int h = tid >> 2, ws = tid & 3;   // outputs w = 16ws..16ws+15, row h
  ull A[8];
  #pragma unroll
  for (int m = 0; m < 8; m++) A[m] = pk(t1, t1);

  #pragma unroll
  for (int r = 0; r < 5; r++) {
    const float* row = &tile[(h + r) * PITCH + 16 * ws];
    float4 c0 = *reinterpret_cast<const float4*>(row);
    float4 c1 = *reinterpret_cast<const float4*>(row + 4);
    float4 c2v = *reinterpret_cast<const float4*>(row + 8);
    float4 c3 = *reinterpret_cast<const float4*>(row + 12);
    float4 c4 = *reinterpret_cast<const float4*>(row + 16);
    ull E[10] = {pk(c0.x, c0.y), pk(c0.z, c0.w), pk(c1.x, c1.y), pk(c1.z, c1.w),
                 pk(c2v.x, c2v.y), pk(c2v.z, c2v.w), pk(c3.x, c3.y),
                 pk(c3.z, c3.w), pk(c4.x, c4.y), pk(c4.z, c4.w)};
    ull O[9]  = {pk(c0.y, c0.z), pk(c0.w, c1.x), pk(c1.y, c1.z), pk(c1.w, c2v.x),
                 pk(c2v.y, c2v.z), pk(c2v.w, c3.x), pk(c3.y, c3.z),
                 pk(c3.w, c4.x), pk(c4.y, c4.z)};
    const ull* Wr = &W[r * 5];
    #pragma unroll
    for (int m = 0; m < 8; m++) {
      ull a = A[m];
      a = fma2(Wr[0], E[m], a);
      a = fma2(Wr[1], O[m], a);
      a = fma2(Wr[2], E[m + 1], a);
      a = fma2(Wr[3], O[m + 1], a);
      a = fma2(Wr[4], E[m + 2], a);
      A[m] = a;
    }
  }

  unsigned hh[8];
  #pragma unroll
  for (int m = 0; m < 8; m++) {
    float a0, a1; upk(a0, a1, A[m]);
    __half2 p2 = __floats2half2_rn(silu_f(a0), silu_f(a1));
    hh[m] = *reinterpret_cast<unsigned*>(&p2);
  }
  unsigned* yp = reinterpret_cast<unsigned*>(g_y1) + (size_t)p * 2048 + h * 32 + 8 * ws;
  *reinterpret_cast<uint4*>(yp)     = make_uint4(hh[0], hh[1], hh[2], hh[3]);
  *reinterpret_cast<uint4*>(yp + 4) = make_uint4(hh[4], hh[5], hh[6], hh[7]);
}

// ---------------- kernel 2: pointwise + attn + top-38 + output ------------
__device__ __forceinline__ float attn_c(int c, size_t idx, const ull* hb2) {
  ull acc = pk(c2.b2[c], 0.0f);
  #pragma unroll
  for (int j = 0; j < 4; j++) acc = fma2(c2.w2o[c * 4 + j], hb2[j], acc);
  float lo, hi; upk(lo, hi, acc);
  float y1v = __half2float(g_y1[idx + (size_t)c * 65536]);
  return y1v * (lo + hi);
}

#define CEA(i, l) { float a_ = s[i], b_ = s[l]; \
                    s[i] = fminf(a_, b_); s[l] = fmaxf(a_, b_); }

__global__ void __launch_bounds__(256)
k_attn(const float* __restrict__ x, float* __restrict__ out) {
  int t = blockIdx.x * 256 + threadIdx.x;   // location 0..262143
  int b = t >> 16;
  int sp = t & 65535;
  size_t xb = (size_t)b * 4194304 + (size_t)sp;   // + c*65536

  // pass 1: 8 hidden pre-activations, packed over o-pairs
  ull h2[4] = {c2.b1o[0], c2.b1o[1], c2.b1o[2], c2.b1o[3]};
  #pragma unroll
  for (int c = 0; c < 64; c++) {
    float xv = __ldg(x + xb + (size_t)c * 65536);
    ull xx = pk(xv, xv);
    #pragma unroll
    for (int j = 0; j < 4; j++) h2[j] = fma2(c2.w1o[c * 4 + j], xx, h2[j]);
  }
  ull hb2[4];
  #pragma unroll
  for (int j = 0; j < 4; j++) {
    float u, v; upk(u, v, h2[j]);
    hb2[j] = pk(silu_f(u), silu_f(v));
  }

  // pass 2: attn values
  float s[64];
  #pragma unroll
  for (int c = 0; c < 64; c++) s[c] = attn_c(c, xb, hb2);

  // bitonic stages k=2..32 (full)
  #pragma unroll
  for (int k = 2; k <= 32; k <<= 1) {
    #pragma unroll
    for (int j = k >> 1; j > 0; j >>= 1) {
      #pragma unroll
      for (int i = 0; i < 64; i++) {
        int l = i ^ j;
        if (l > i) {
          float a = s[i], bz = s[l];
          float lo = fminf(a, bz), hi = fmaxf(a, bz);
          if ((i & k) == 0) { s[i] = lo; s[l] = hi; }
          else              { s[i] = hi; s[l] = lo; }
        }
      }
    }
  }
  // final k=64 merge, pruned to the dependence cone of index 26 (63 CE)
  #pragma unroll
  for (int i = 0; i < 32; i++) CEA(i, i + 32);
  #pragma unroll
  for (int i = 0; i < 16; i++) CEA(i, i + 16);
  #pragma unroll
  for (int i = 16; i < 24; i++) CEA(i, i + 8);
  #pragma unroll
  for (int i = 24; i < 28; i++) CEA(i, i + 4);
  CEA(24, 26); CEA(25, 27);
  CEA(26, 27);
  float thr = s[26];
  float alpha = c2.alpha;

  // pass 3: recompute attn (bit-identical) + write out
  #pragma unroll
  for (int c = 0; c < 64; c++) {
    float a  = attn_c(c, xb, hb2);
    float xv = __ldg(x + xb + (size_t)c * 65536);
    float r  = (a >= thr) ? fmaf(alpha, a, xv) : xv;
    out[xb + (size_t)c * 65536] = r;
  }
}

// ---------------------------------------------------------------------------
extern "C" void kernel_launch(void* const* d_in, const int* in_sizes, int n_in,
                              void* d_out, int out_size) {
  const float* x    = (const float*)d_in[0];
  const float* wdw  = (const float*)d_in[1];
  const float* g1   = (const float*)d_in[2];
  const float* be1  = (const float*)d_in[3];
  const float* m1   = (const float*)d_in[4];
  const float* v1   = (const float*)d_in[5];
  const float* wp1  = (const float*)d_in[6];
  const float* bp1  = (const float*)d_in[7];
  const float* g2   = (const float*)d_in[8];
  const float* be2  = (const float*)d_in[9];
  const float* m2   = (const float*)d_in[10];
  const float* v2   = (const float*)d_in[11];
  const float* wp2  = (const float*)d_in[12];
  const float* bp2  = (const float*)d_in[13];
  const float* alpha= (const float*)d_in[14];
  float* out = (float*)d_out;

  kprep<<<1, 256>>>(wp1, bp1, g2, be2, m2, v2, wp2, bp2, alpha);
  void* gaddr = nullptr;
  cudaGetSymbolAddress(&gaddr, g_c2);
  cudaMemcpyToSymbolAsync(c2, gaddr, sizeof(C2), 0,
                          cudaMemcpyDeviceToDevice, 0);
  k_dwconv<<<4096, 256>>>(x, wdw, g1, be1, m1, v1);
  k_attn<<<1024, 256>>>(x, out);
}

// round 5
// speedup vs baseline: 1.4917x; 1.4917x over previous
#include <cuda_runtime.h>
#include <cuda_fp16.h>

// B=4, C=64, D=16, H=64, W=64, C8=8, k=38 -> thr = sorted_ascending[26]
#define EPSBN 1e-5f
typedef unsigned long long ull;

// ---------------- packed f32x2 helpers (fma pipe only) ----------------
__device__ __forceinline__ ull pk(float lo, float hi) {
  ull r; asm("mov.b64 %0,{%1,%2};" : "=l"(r) : "f"(lo), "f"(hi)); return r;
}
__device__ __forceinline__ void upk(float& lo, float& hi, ull v) {
  asm("mov.b64 {%0,%1},%2;" : "=f"(lo), "=f"(hi) : "l"(v));
}
__device__ __forceinline__ ull fma2(ull a, ull b, ull c) {
  ull d; asm("fma.rn.f32x2 %0,%1,%2,%3;" : "=l"(d) : "l"(a), "l"(b), "l"(c)); return d;
}
__device__ __forceinline__ float silu_f(float v) {
  return v * (1.0f / (1.0f + __expf(-v)));
}

// ---------------- params ----------------
struct C2 {
  ull w1o[256];   // [c*4+j] = pk(w1t[c][2j], w1t[c][2j+1]), bn2 scale folded
  ull w2o[256];   // [c*4+j] = pk(w2[c][2j], w2[c][2j+1])
  ull b1o[4];     // pk(b1_eff[2j], b1_eff[2j+1])
  float b2[64];
  float alpha;
};
__device__   C2 g_c2;
__constant__ C2 c2;
__device__ __half g_y1[16777216];   // 32MB; same linear indexing as x

// ---------------- kernel 1: depthwise conv + BN + SiLU -> fp16 y1 ----------
// Round-1 proven mapping: wq = tid&15 (4-wide), hb = tid>>4, 4 row-groups.
// Block 0 additionally folds the pointwise params into g_c2.
#define T1PITCH 72
__global__ void __launch_bounds__(256)
k_dwconv(const float* __restrict__ x,
         const float* __restrict__ wdw,
         const float* __restrict__ g1, const float* __restrict__ be1,
         const float* __restrict__ m1, const float* __restrict__ v1,
         const float* __restrict__ wp1, const float* __restrict__ bp1,
         const float* __restrict__ g2, const float* __restrict__ be2,
         const float* __restrict__ m2, const float* __restrict__ v2,
         const float* __restrict__ wp2, const float* __restrict__ bp2,
         const float* __restrict__ alpha) {
  __shared__ float tile[68 * T1PITCH];
  int p = blockIdx.x;               // ((b*64+c)*16+d)
  int c = (p >> 4) & 63;
  int tid = threadIdx.x;

  // block 0: fold pointwise params (runs alongside its conv work)
  if (p == 0) {
    int cc = tid >> 2, j = tid & 3;
    int o0 = 2 * j, o1 = o0 + 1;
    float s2a = __ldg(g2 + o0) * rsqrtf(__ldg(v2 + o0) + EPSBN);
    float s2b = __ldg(g2 + o1) * rsqrtf(__ldg(v2 + o1) + EPSBN);
    g_c2.w1o[cc * 4 + j] = pk(__ldg(wp1 + o0 * 64 + cc) * s2a,
                              __ldg(wp1 + o1 * 64 + cc) * s2b);
    g_c2.w2o[cc * 4 + j] = pk(__ldg(wp2 + cc * 8 + o0), __ldg(wp2 + cc * 8 + o1));
    if (tid < 4) {
      int p0 = 2 * tid, p1 = p0 + 1;
      float sa = __ldg(g2 + p0) * rsqrtf(__ldg(v2 + p0) + EPSBN);
      float sb = __ldg(g2 + p1) * rsqrtf(__ldg(v2 + p1) + EPSBN);
      g_c2.b1o[tid] = pk((__ldg(bp1 + p0) - __ldg(m2 + p0)) * sa + __ldg(be2 + p0),
                         (__ldg(bp1 + p1) - __ldg(m2 + p1)) * sb + __ldg(be2 + p1));
    }
    if (tid < 64) g_c2.b2[tid] = __ldg(bp2 + tid);
    if (tid == 0) g_c2.alpha = __ldg(alpha);
  }

  // zero halo region, load plane
  for (int i = tid; i < 68 * T1PITCH; i += 256) tile[i] = 0.f;
  __syncthreads();
  const float* xp = x + (size_t)p * 4096;
  #pragma unroll
  for (int it = 0; it < 4; it++) {
    int i = tid + it * 256;
    int h = i >> 4, q = i & 15;
    float4 v = *reinterpret_cast<const float4*>(xp + h * 64 + q * 4);
    float* dst = &tile[(h + 2) * T1PITCH + q * 4 + 2];
    dst[0] = v.x; dst[1] = v.y; dst[2] = v.z; dst[3] = v.w;
  }
  __syncthreads();

  float s1 = __ldg(g1 + c) * rsqrtf(__ldg(v1 + c) + EPSBN);
  float t1 = __ldg(be1 + c) - __ldg(m1 + c) * s1;
  float wk[25];
  #pragma unroll
  for (int j = 0; j < 25; j++) wk[j] = __ldg(wdw + c * 25 + j) * s1;

  int wq = tid & 15;        // outputs w = 4wq..4wq+3
  int hb = tid >> 4;
  __half2* yp2 = reinterpret_cast<__half2*>(g_y1) + (size_t)p * 2048;

  #pragma unroll
  for (int g = 0; g < 4; g++) {
    int h = hb + g * 16;
    float a0 = t1, a1 = t1, a2 = t1, a3 = t1;
    #pragma unroll
    for (int r = 0; r < 5; r++) {
      const float* row = &tile[(h + r) * T1PITCH + 4 * wq];
      float4 va = *reinterpret_cast<const float4*>(row);
      float4 vb = *reinterpret_cast<const float4*>(row + 4);
      const float* wr = &wk[r * 5];
      a0 = fmaf(wr[0], va.x, fmaf(wr[1], va.y, fmaf(wr[2], va.z, fmaf(wr[3], va.w, fmaf(wr[4], vb.x, a0)))));
      a1 = fmaf(wr[0], va.y, fmaf(wr[1], va.z, fmaf(wr[2], va.w, fmaf(wr[3], vb.x, fmaf(wr[4], vb.y, a1)))));
      a2 = fmaf(wr[0], va.z, fmaf(wr[1], va.w, fmaf(wr[2], vb.x, fmaf(wr[3], vb.y, fmaf(wr[4], vb.z, a2)))));
      a3 = fmaf(wr[0], va.w, fmaf(wr[1], vb.x, fmaf(wr[2], vb.y, fmaf(wr[3], vb.z, fmaf(wr[4], vb.w, a3)))));
    }
    __half2 h0 = __floats2half2_rn(silu_f(a0), silu_f(a1));
    __half2 h1 = __floats2half2_rn(silu_f(a2), silu_f(a3));
    // half2 index: h*32 + 2wq ; uint2 = both half2s (8B aligned)
    __half2* dst = yp2 + h * 32 + 2 * wq;
    dst[0] = h0; dst[1] = h1;
  }
}

// ---------------- kernel 2: pointwise + attn + top-38 + output ------------
#define CEA(i, l) { float a_ = s[i], b_ = s[l]; \
                    s[i] = fminf(a_, b_); s[l] = fmaxf(a_, b_); }

__global__ void __launch_bounds__(256, 2)
k_attn(const float* __restrict__ x, float* __restrict__ out) {
  extern __shared__ float park[];           // 64*256 floats = 64KB
  int tid = threadIdx.x;
  int t = blockIdx.x * 256 + tid;
  int b = t >> 16;
  int sp = t & 65535;
  size_t xb = (size_t)b * 4194304 + (size_t)sp;   // + c*65536

  // pass 1: 8 hidden pre-activations (packed over o-pairs)
  ull h2[4] = {c2.b1o[0], c2.b1o[1], c2.b1o[2], c2.b1o[3]};
  #pragma unroll
  for (int c = 0; c < 64; c++) {
    float xv = __ldg(x + xb + (size_t)c * 65536);
    ull xx = pk(xv, xv);
    #pragma unroll
    for (int j = 0; j < 4; j++) h2[j] = fma2(c2.w1o[c * 4 + j], xx, h2[j]);
  }
  ull hb2[4];
  #pragma unroll
  for (int j = 0; j < 4; j++) {
    float u, v; upk(u, v, h2[j]);
    hb2[j] = pk(silu_f(u), silu_f(v));
  }

  // pass 2: attn values -> regs (for sort) + smem park (for output pass)
  float s[64];
  #pragma unroll
  for (int c = 0; c < 64; c++) {
    ull acc = pk(c2.b2[c], 0.0f);
    #pragma unroll
    for (int j = 0; j < 4; j++) acc = fma2(c2.w2o[c * 4 + j], hb2[j], acc);
    float lo, hi; upk(lo, hi, acc);
    float y1v = __half2float(__ldg(g_y1 + xb + (size_t)c * 65536));
    float a = y1v * (lo + hi);
    park[c * 256 + tid] = a;
    s[c] = a;
  }

  // bitonic stages k=2..32 (full; sorts both halves)
  #pragma unroll
  for (int k = 2; k <= 32; k <<= 1) {
    #pragma unroll
    for (int j = k >> 1; j > 0; j >>= 1) {
      #pragma unroll
      for (int i = 0; i < 64; i++) {
        int l = i ^ j;
        if (l > i) {
          float a = s[i], bz = s[l];
          float lo = fminf(a, bz), hi = fmaxf(a, bz);
          if ((i & k) == 0) { s[i] = lo; s[l] = hi; }
          else              { s[i] = hi; s[l] = lo; }
        }
      }
    }
  }
  // final k=64 merge pruned to dependence cone of index 26 (63 CE)
  #pragma unroll
  for (int i = 0; i < 32; i++) CEA(i, i + 32);
  #pragma unroll
  for (int i = 0; i < 16; i++) CEA(i, i + 16);
  #pragma unroll
  for (int i = 16; i < 24; i++) CEA(i, i + 8);
  #pragma unroll
  for (int i = 24; i < 28; i++) CEA(i, i + 4);
  CEA(24, 26); CEA(25, 27);
  CEA(26, 27);
  float thr = s[26];
  float alpha = c2.alpha;

  // pass 3: read parked attn (bit-identical) + write out
  #pragma unroll
  for (int c = 0; c < 64; c++) {
    float a  = park[c * 256 + tid];
    float xv = __ldg(x + xb + (size_t)c * 65536);
    float r  = (a >= thr) ? fmaf(alpha, a, xv) : xv;
    out[xb + (size_t)c * 65536] = r;
  }
}

// ---------------------------------------------------------------------------
extern "C" void kernel_launch(void* const* d_in, const int* in_sizes, int n_in,
                              void* d_out, int out_size) {
  const float* x    = (const float*)d_in[0];
  const float* wdw  = (const float*)d_in[1];
  const float* g1   = (const float*)d_in[2];
  const float* be1  = (const float*)d_in[3];
  const float* m1   = (const float*)d_in[4];
  const float* v1   = (const float*)d_in[5];
  const float* wp1  = (const float*)d_in[6];
  const float* bp1  = (const float*)d_in[7];
  const float* g2   = (const float*)d_in[8];
  const float* be2  = (const float*)d_in[9];
  const float* m2   = (const float*)d_in[10];
  const float* v2   = (const float*)d_in[11];
  const float* wp2  = (const float*)d_in[12];
  const float* bp2  = (const float*)d_in[13];
  const float* alpha= (const float*)d_in[14];
  float* out = (float*)d_out;

  k_dwconv<<<4096, 256>>>(x, wdw, g1, be1, m1, v1, wp1, bp1,
                          g2, be2, m2, v2, wp2, bp2, alpha);

  void* gaddr = nullptr;
  cudaGetSymbolAddress(&gaddr, g_c2);
  cudaMemcpyToSymbolAsync(c2, gaddr, sizeof(C2), 0,
                          cudaMemcpyDeviceToDevice, 0);

  cudaFuncSetAttribute(k_attn, cudaFuncAttributeMaxDynamicSharedMemorySize,
                       65536);
  k_attn<<<1024, 256, 65536>>>(x, out);
}